// round 1
// baseline (speedup 1.0000x reference)
#include <cuda_runtime.h>
#include <cstdint>

// Problem constants (fixed shapes for this problem)
#define BQ   28800      // B*Q = 32*900
#define CNUM 92
#define TNUM 2048
#define RB   96         // rows per block tile (96*92*4 + 96*48 < 48KB static smem)

// Scratch (allocation-free rule: __device__ globals)
__device__ __align__(16) float  g_prob[BQ * CNUM];   // 2 - softmax(logits)
__device__ __align__(16) float4 g_tf[TNUM * 3];      // per-target: {cx,cy,w,h},{x0,y0,x1,y1},{area,label_bits,0,0}

// ---------------------------------------------------------------------------
// Phase 1a: row softmax, store (2 - prob) so the GIoU "+2" constant is folded in.
// One warp per row; C=92 = 32+32+28 per lane.
// ---------------------------------------------------------------------------
__global__ __launch_bounds__(256) void softmax_kernel(const float* __restrict__ logits) {
    int row  = blockIdx.x * 8 + (threadIdx.x >> 5);
    int lane = threadIdx.x & 31;
    if (row >= BQ) return;
    const float* in = logits + (size_t)row * CNUM;

    float v0 = in[lane];
    float v1 = in[lane + 32];
    float v2 = (lane < 28) ? in[lane + 64] : -3.402823e38f;

    float m = fmaxf(fmaxf(v0, v1), v2);
    #pragma unroll
    for (int o = 16; o > 0; o >>= 1) m = fmaxf(m, __shfl_xor_sync(0xffffffffu, m, o));

    float e0 = __expf(v0 - m);
    float e1 = __expf(v1 - m);
    float e2 = (lane < 28) ? __expf(v2 - m) : 0.f;

    float s = e0 + e1 + e2;
    #pragma unroll
    for (int o = 16; o > 0; o >>= 1) s += __shfl_xor_sync(0xffffffffu, s, o);

    float inv = __fdividef(1.f, s);
    float* op = g_prob + (size_t)row * CNUM;
    op[lane]      = 2.f - e0 * inv;
    op[lane + 32] = 2.f - e1 * inv;
    if (lane < 28) op[lane + 64] = 2.f - e2 * inv;
}

// ---------------------------------------------------------------------------
// Phase 1b: target features (xyxy, area, label) precomputed once.
// ---------------------------------------------------------------------------
__global__ __launch_bounds__(256) void tfeat_kernel(const float* __restrict__ tgt_boxes,
                                                    const int*   __restrict__ tgt_labels) {
    int t = blockIdx.x * blockDim.x + threadIdx.x;
    if (t >= TNUM) return;
    float4 b = reinterpret_cast<const float4*>(tgt_boxes)[t];
    float hw = 0.5f * b.z, hh = 0.5f * b.w;
    g_tf[t * 3 + 0] = b;
    g_tf[t * 3 + 1] = make_float4(b.x - hw, b.y - hh, b.x + hw, b.y + hh);
    g_tf[t * 3 + 2] = make_float4(b.z * b.w, __int_as_float(tgt_labels[t]), 0.f, 0.f);
}

// ---------------------------------------------------------------------------
// Pairwise cost: gmod = (2 - prob[row][label])  already includes class term + GIoU const.
// cost = gmod + 5*L1 - 2*inter/union - 2*union/enclosing
// ---------------------------------------------------------------------------
__device__ __forceinline__ float pair_cost(
    float4 rb, float4 rx, float rArea,      // row: cxcywh, xyxy, area
    float4 tb, float4 tx, float tArea,      // target
    float gmod)
{
    float l1 = fabsf(rb.x - tb.x) + fabsf(rb.y - tb.y)
             + fabsf(rb.z - tb.z) + fabsf(rb.w - tb.w);

    float ltx = fmaxf(rx.x, tx.x), lty = fmaxf(rx.y, tx.y);
    float rbx = fminf(rx.z, tx.z), rby = fminf(rx.w, tx.w);
    float wi  = fmaxf(rbx - ltx, 0.f);
    float hi  = fmaxf(rby - lty, 0.f);
    float inter = wi * hi;
    float uni   = (rArea + tArea) - inter;

    float ex0 = fminf(rx.x, tx.x), ey0 = fminf(rx.y, tx.y);
    float ex1 = fmaxf(rx.z, tx.z), ey1 = fmaxf(rx.w, tx.w);
    float areaE = (ex1 - ex0) * (ey1 - ey0);

    float t1 = __fdividef(inter, uni);
    float t2 = __fdividef(uni, areaE);

    return fmaf(5.f, l1, gmod) - 2.f * (t1 + t2);
}

// ---------------------------------------------------------------------------
// Phase 2: main cost kernel.
// Block = 256 threads. Each thread owns 2 consecutive targets (feats in regs),
// loops over a tile of RB rows (row feats + probmod row staged in smem).
// Stores are float2, fully coalesced along t.
// ---------------------------------------------------------------------------
__global__ __launch_bounds__(256) void cost_kernel(const float* __restrict__ pred_boxes,
                                                   float* __restrict__ out) {
    __shared__ float  sProb[RB * CNUM];   // 96*92*4 = 35328 B
    __shared__ float4 sFeat[RB * 3];      // 96*48   =  4608 B

    const int tid = threadIdx.x;
    const int r0  = blockIdx.x * RB;
    const int t0  = blockIdx.y * 512 + tid * 2;

    // Stage probmod rows (contiguous float4 copies)
    {
        const float4* gp = reinterpret_cast<const float4*>(g_prob + (size_t)r0 * CNUM);
        float4* sp = reinterpret_cast<float4*>(sProb);
        #pragma unroll 1
        for (int i = tid; i < RB * (CNUM / 4); i += 256) sp[i] = gp[i];
    }
    // Row features
    if (tid < RB) {
        float4 b = reinterpret_cast<const float4*>(pred_boxes)[r0 + tid];
        float hw = 0.5f * b.z, hh = 0.5f * b.w;
        sFeat[tid * 3 + 0] = b;
        sFeat[tid * 3 + 1] = make_float4(b.x - hw, b.y - hh, b.x + hw, b.y + hh);
        sFeat[tid * 3 + 2] = make_float4(b.z * b.w, 0.f, 0.f, 0.f);
    }
    __syncthreads();

    // This thread's two targets -> registers
    float4 A0 = g_tf[t0 * 3 + 0], A1 = g_tf[t0 * 3 + 1], A2 = g_tf[t0 * 3 + 2];
    float4 B0 = g_tf[t0 * 3 + 3], B1 = g_tf[t0 * 3 + 4], B2 = g_tf[t0 * 3 + 5];
    const int la = __float_as_int(A2.y);
    const int lb = __float_as_int(B2.y);

    float2* op = reinterpret_cast<float2*>(out + (size_t)r0 * TNUM + t0);
    const int strideF2 = TNUM / 2;

    #pragma unroll 2
    for (int i = 0; i < RB; i++) {
        float4 rb = sFeat[i * 3 + 0];
        float4 rx = sFeat[i * 3 + 1];
        float  rA = sFeat[i * 3 + 2].x;
        const float* pr = sProb + i * CNUM;

        float ga = pr[la];
        float gb = pr[lb];

        float ca = pair_cost(rb, rx, rA, A0, A1, A2.x, ga);
        float cb = pair_cost(rb, rx, rA, B0, B1, B2.x, gb);

        op[(size_t)i * strideF2] = make_float2(ca, cb);
    }
}

// ---------------------------------------------------------------------------
extern "C" void kernel_launch(void* const* d_in, const int* in_sizes, int n_in,
                              void* d_out, int out_size) {
    const float* logits  = (const float*)d_in[0];   // [32,900,92] f32
    const float* pboxes  = (const float*)d_in[1];   // [32,900,4]  f32
    const int*   tlabels = (const int*)  d_in[2];   // [2048] i32
    const float* tboxes  = (const float*)d_in[3];   // [2048,4] f32
    float* out = (float*)d_out;                      // [32,900,2048] f32

    softmax_kernel<<<BQ / 8, 256>>>(logits);
    tfeat_kernel<<<TNUM / 256, 256>>>(tboxes, tlabels);

    dim3 grid(BQ / RB, TNUM / 512);  // (300, 4)
    cost_kernel<<<grid, 256>>>(pboxes, out);
}

// round 2
// speedup vs baseline: 1.0003x; 1.0003x over previous
#include <cuda_runtime.h>
#include <cstdint>

// Problem constants (fixed shapes for this problem)
#define BQ   28800      // B*Q = 32*900
#define CNUM 92
#define TNUM 2048
#define RB   96         // rows per block tile (96*92*4 + 96*48 < 48KB static smem)

// Scratch (allocation-free rule: __device__ globals)
__device__ __align__(16) float  g_prob[BQ * CNUM];   // 2 - softmax(logits)
__device__ __align__(16) float4 g_tf[TNUM * 3];      // per-target: {cx,cy,w,h},{x0,y0,x1,y1},{area,label_bits,0,0}

// ---------------------------------------------------------------------------
// Phase 1a: row softmax, store (2 - prob) so the GIoU "+2" constant is folded in.
// One warp per row; C=92 = 32+32+28 per lane.
// ---------------------------------------------------------------------------
__global__ __launch_bounds__(256) void softmax_kernel(const float* __restrict__ logits) {
    int row  = blockIdx.x * 8 + (threadIdx.x >> 5);
    int lane = threadIdx.x & 31;
    if (row >= BQ) return;
    const float* in = logits + (size_t)row * CNUM;

    float v0 = in[lane];
    float v1 = in[lane + 32];
    float v2 = (lane < 28) ? in[lane + 64] : -3.402823e38f;

    float m = fmaxf(fmaxf(v0, v1), v2);
    #pragma unroll
    for (int o = 16; o > 0; o >>= 1) m = fmaxf(m, __shfl_xor_sync(0xffffffffu, m, o));

    float e0 = __expf(v0 - m);
    float e1 = __expf(v1 - m);
    float e2 = (lane < 28) ? __expf(v2 - m) : 0.f;

    float s = e0 + e1 + e2;
    #pragma unroll
    for (int o = 16; o > 0; o >>= 1) s += __shfl_xor_sync(0xffffffffu, s, o);

    float inv = __fdividef(1.f, s);
    float* op = g_prob + (size_t)row * CNUM;
    op[lane]      = 2.f - e0 * inv;
    op[lane + 32] = 2.f - e1 * inv;
    if (lane < 28) op[lane + 64] = 2.f - e2 * inv;
}

// ---------------------------------------------------------------------------
// Phase 1b: target features (xyxy, area, label) precomputed once.
// ---------------------------------------------------------------------------
__global__ __launch_bounds__(256) void tfeat_kernel(const float* __restrict__ tgt_boxes,
                                                    const int*   __restrict__ tgt_labels) {
    int t = blockIdx.x * blockDim.x + threadIdx.x;
    if (t >= TNUM) return;
    float4 b = reinterpret_cast<const float4*>(tgt_boxes)[t];
    float hw = 0.5f * b.z, hh = 0.5f * b.w;
    g_tf[t * 3 + 0] = b;
    g_tf[t * 3 + 1] = make_float4(b.x - hw, b.y - hh, b.x + hw, b.y + hh);
    g_tf[t * 3 + 2] = make_float4(b.z * b.w, __int_as_float(tgt_labels[t]), 0.f, 0.f);
}

// ---------------------------------------------------------------------------
// Pairwise cost: gmod = (2 - prob[row][label])  already includes class term + GIoU const.
// cost = gmod + 5*L1 - 2*inter/union - 2*union/enclosing
// ---------------------------------------------------------------------------
__device__ __forceinline__ float pair_cost(
    float4 rb, float4 rx, float rArea,      // row: cxcywh, xyxy, area
    float4 tb, float4 tx, float tArea,      // target
    float gmod)
{
    float l1 = fabsf(rb.x - tb.x) + fabsf(rb.y - tb.y)
             + fabsf(rb.z - tb.z) + fabsf(rb.w - tb.w);

    float ltx = fmaxf(rx.x, tx.x), lty = fmaxf(rx.y, tx.y);
    float rbx = fminf(rx.z, tx.z), rby = fminf(rx.w, tx.w);
    float wi  = fmaxf(rbx - ltx, 0.f);
    float hi  = fmaxf(rby - lty, 0.f);
    float inter = wi * hi;
    float uni   = (rArea + tArea) - inter;

    float ex0 = fminf(rx.x, tx.x), ey0 = fminf(rx.y, tx.y);
    float ex1 = fmaxf(rx.z, tx.z), ey1 = fmaxf(rx.w, tx.w);
    float areaE = (ex1 - ex0) * (ey1 - ey0);

    float t1 = __fdividef(inter, uni);
    float t2 = __fdividef(uni, areaE);

    return fmaf(5.f, l1, gmod) - 2.f * (t1 + t2);
}

// ---------------------------------------------------------------------------
// Phase 2: main cost kernel.
// Block = 256 threads. Each thread owns 2 consecutive targets (feats in regs),
// loops over a tile of RB rows (row feats + probmod row staged in smem).
// Stores are float2, fully coalesced along t.
// ---------------------------------------------------------------------------
__global__ __launch_bounds__(256) void cost_kernel(const float* __restrict__ pred_boxes,
                                                   float* __restrict__ out) {
    __shared__ float  sProb[RB * CNUM];   // 96*92*4 = 35328 B
    __shared__ float4 sFeat[RB * 3];      // 96*48   =  4608 B

    const int tid = threadIdx.x;
    const int r0  = blockIdx.x * RB;
    const int t0  = blockIdx.y * 512 + tid * 2;

    // Stage probmod rows (contiguous float4 copies)
    {
        const float4* gp = reinterpret_cast<const float4*>(g_prob + (size_t)r0 * CNUM);
        float4* sp = reinterpret_cast<float4*>(sProb);
        #pragma unroll 1
        for (int i = tid; i < RB * (CNUM / 4); i += 256) sp[i] = gp[i];
    }
    // Row features
    if (tid < RB) {
        float4 b = reinterpret_cast<const float4*>(pred_boxes)[r0 + tid];
        float hw = 0.5f * b.z, hh = 0.5f * b.w;
        sFeat[tid * 3 + 0] = b;
        sFeat[tid * 3 + 1] = make_float4(b.x - hw, b.y - hh, b.x + hw, b.y + hh);
        sFeat[tid * 3 + 2] = make_float4(b.z * b.w, 0.f, 0.f, 0.f);
    }
    __syncthreads();

    // This thread's two targets -> registers
    float4 A0 = g_tf[t0 * 3 + 0], A1 = g_tf[t0 * 3 + 1], A2 = g_tf[t0 * 3 + 2];
    float4 B0 = g_tf[t0 * 3 + 3], B1 = g_tf[t0 * 3 + 4], B2 = g_tf[t0 * 3 + 5];
    const int la = __float_as_int(A2.y);
    const int lb = __float_as_int(B2.y);

    float2* op = reinterpret_cast<float2*>(out + (size_t)r0 * TNUM + t0);
    const int strideF2 = TNUM / 2;

    #pragma unroll 2
    for (int i = 0; i < RB; i++) {
        float4 rb = sFeat[i * 3 + 0];
        float4 rx = sFeat[i * 3 + 1];
        float  rA = sFeat[i * 3 + 2].x;
        const float* pr = sProb + i * CNUM;

        float ga = pr[la];
        float gb = pr[lb];

        float ca = pair_cost(rb, rx, rA, A0, A1, A2.x, ga);
        float cb = pair_cost(rb, rx, rA, B0, B1, B2.x, gb);

        op[(size_t)i * strideF2] = make_float2(ca, cb);
    }
}

// ---------------------------------------------------------------------------
extern "C" void kernel_launch(void* const* d_in, const int* in_sizes, int n_in,
                              void* d_out, int out_size) {
    const float* logits  = (const float*)d_in[0];   // [32,900,92] f32
    const float* pboxes  = (const float*)d_in[1];   // [32,900,4]  f32
    const int*   tlabels = (const int*)  d_in[2];   // [2048] i32
    const float* tboxes  = (const float*)d_in[3];   // [2048,4] f32
    float* out = (float*)d_out;                      // [32,900,2048] f32

    softmax_kernel<<<BQ / 8, 256>>>(logits);
    tfeat_kernel<<<TNUM / 256, 256>>>(tboxes, tlabels);

    dim3 grid(BQ / RB, TNUM / 512);  // (300, 4)
    cost_kernel<<<grid, 256>>>(pboxes, out);
}

// round 3
// speedup vs baseline: 1.2877x; 1.2873x over previous
#include <cuda_runtime.h>
#include <cstdint>

// Problem constants (fixed shapes)
#define BQ   28800      // B*Q = 32*900
#define CNUM 92
#define TNUM 2048
#define RB   96         // rows per block tile

// Scratch (allocation-free rule: __device__ globals)
__device__ __align__(16) float  g_prob[BQ * CNUM];   // 2 - softmax(logits)
__device__ __align__(16) float4 g_tf[TNUM * 3];      // {cx,cy,w,h},{x0,y0,x1,y1},{area,label_bits,0,0}

// ---------------------------------------------------------------------------
// Packed f32x2 helpers (Blackwell sm_100+): 2 floats per fma-pipe instruction.
// ---------------------------------------------------------------------------
union P2 { unsigned long long u; float2 f; };

__device__ __forceinline__ P2 mk2(float x, float y) { P2 r; r.f = make_float2(x, y); return r; }
__device__ __forceinline__ P2 add2(P2 a, P2 b) { P2 r; asm("add.rn.f32x2 %0,%1,%2;" : "=l"(r.u) : "l"(a.u), "l"(b.u)); return r; }
__device__ __forceinline__ P2 sub2(P2 a, P2 b) { P2 r; asm("sub.rn.f32x2 %0,%1,%2;" : "=l"(r.u) : "l"(a.u), "l"(b.u)); return r; }
__device__ __forceinline__ P2 mul2(P2 a, P2 b) { P2 r; asm("mul.rn.f32x2 %0,%1,%2;" : "=l"(r.u) : "l"(a.u), "l"(b.u)); return r; }
__device__ __forceinline__ P2 fma2(P2 a, P2 b, P2 c) { P2 r; asm("fma.rn.f32x2 %0,%1,%2,%3;" : "=l"(r.u) : "l"(a.u), "l"(b.u), "l"(c.u)); return r; }
__device__ __forceinline__ float frcp(float x) { float r; asm("rcp.approx.ftz.f32 %0,%1;" : "=f"(r) : "f"(x)); return r; }

// ---------------------------------------------------------------------------
// Phase 1a: row softmax, store (2 - prob): folds class cost sign + GIoU "+2".
// ---------------------------------------------------------------------------
__global__ __launch_bounds__(256) void softmax_kernel(const float* __restrict__ logits) {
    int row  = blockIdx.x * 8 + (threadIdx.x >> 5);
    int lane = threadIdx.x & 31;
    if (row >= BQ) return;
    const float* in = logits + (size_t)row * CNUM;

    float v0 = in[lane];
    float v1 = in[lane + 32];
    float v2 = (lane < 28) ? in[lane + 64] : -3.402823e38f;

    float m = fmaxf(fmaxf(v0, v1), v2);
    #pragma unroll
    for (int o = 16; o > 0; o >>= 1) m = fmaxf(m, __shfl_xor_sync(0xffffffffu, m, o));

    float e0 = __expf(v0 - m);
    float e1 = __expf(v1 - m);
    float e2 = (lane < 28) ? __expf(v2 - m) : 0.f;

    float s = e0 + e1 + e2;
    #pragma unroll
    for (int o = 16; o > 0; o >>= 1) s += __shfl_xor_sync(0xffffffffu, s, o);

    float inv = __fdividef(1.f, s);
    float* op = g_prob + (size_t)row * CNUM;
    op[lane]      = 2.f - e0 * inv;
    op[lane + 32] = 2.f - e1 * inv;
    if (lane < 28) op[lane + 64] = 2.f - e2 * inv;
}

// ---------------------------------------------------------------------------
// Phase 1b: per-target features.
// ---------------------------------------------------------------------------
__global__ __launch_bounds__(256) void tfeat_kernel(const float* __restrict__ tgt_boxes,
                                                    const int*   __restrict__ tgt_labels) {
    int t = blockIdx.x * blockDim.x + threadIdx.x;
    if (t >= TNUM) return;
    float4 b = reinterpret_cast<const float4*>(tgt_boxes)[t];
    float hw = 0.5f * b.z, hh = 0.5f * b.w;
    g_tf[t * 3 + 0] = b;
    g_tf[t * 3 + 1] = make_float4(b.x - hw, b.y - hh, b.x + hw, b.y + hh);
    g_tf[t * 3 + 2] = make_float4(b.z * b.w, __int_as_float(tgt_labels[t]), 0.f, 0.f);
}

// ---------------------------------------------------------------------------
// Loop-invariant per-thread state for a pack of 2 targets.
// ---------------------------------------------------------------------------
struct TPack {
    P2 cx, cy, w, h, area;          // packed {A,B}
    float ax0, ay0, ax1, ay1;       // target A xyxy (scalar, for FMNMX)
    float bx0, by0, bx1, by1;       // target B xyxy
    int   la, lb;                   // labels
};

// cost for 2 (row, target) pairs, fully packed where the pipes allow.
// Row data: rcx/rcy/rw/rh/rA are {v,v} duplicated packs from smem; rx = row xyxy scalar.
__device__ __forceinline__ P2 pack_cost(
    P2 rcx, P2 rcy, P2 rw, P2 rh, P2 rA, float4 rx,
    const TPack& T, const float* __restrict__ pr, P2 c5, P2 cm2)
{
    // L1 (packed subs, scalar abs-adds: abs folds into FADD source modifiers)
    P2 d0 = sub2(rcx, T.cx);
    P2 d1 = sub2(rcy, T.cy);
    P2 d2 = sub2(rw,  T.w);
    P2 d3 = sub2(rh,  T.h);
    float l1a = (fabsf(d0.f.x) + fabsf(d1.f.x)) + (fabsf(d2.f.x) + fabsf(d3.f.x));
    float l1b = (fabsf(d0.f.y) + fabsf(d1.f.y)) + (fabsf(d2.f.y) + fabsf(d3.f.y));

    // x-dim: intersection width (scalar min/max) + enclosing width via
    // eW = (rw + tw) - (min(x1) - max(x0))   [unclamped]
    float wiua = fminf(rx.z, T.ax1) - fmaxf(rx.x, T.ax0);
    float wiub = fminf(rx.z, T.bx1) - fmaxf(rx.x, T.bx0);
    float wa = fmaxf(wiua, 0.f), wb = fmaxf(wiub, 0.f);
    P2 eWx = sub2(add2(rw, T.w), mk2(wiua, wiub));

    // y-dim
    float hiua = fminf(rx.w, T.ay1) - fmaxf(rx.y, T.ay0);
    float hiub = fminf(rx.w, T.by1) - fmaxf(rx.y, T.by0);
    float ha = fmaxf(hiua, 0.f), hb = fmaxf(hiub, 0.f);
    P2 eHy = sub2(add2(rh, T.h), mk2(hiua, hiub));

    P2 inter = mul2(mk2(wa, wb), mk2(ha, hb));
    P2 E     = mul2(eWx, eHy);
    P2 uni   = sub2(add2(rA, T.area), inter);

    // inter/uni + uni/E == (inter*E + uni^2) * rcp(uni*E)   -> single rcp per pair
    P2 num = fma2(inter, E, mul2(uni, uni));
    P2 den = mul2(uni, E);
    P2 r   = mk2(frcp(den.f.x), frcp(den.f.y));
    P2 q   = mul2(num, r);

    // base = gmod + 5*l1 ;  res = base - 2*q
    P2 base = fma2(c5, mk2(l1a, l1b), mk2(pr[T.la], pr[T.lb]));
    return fma2(cm2, q, base);
}

// ---------------------------------------------------------------------------
// Phase 2: main cost kernel. 256 threads, 4 targets/thread (2 f32x2 packs),
// RB-row tile staged in smem (prob rows + duplicated row features).
// ---------------------------------------------------------------------------
__global__ __launch_bounds__(256) void cost_kernel(const float* __restrict__ pred_boxes,
                                                   float* __restrict__ out) {
    __shared__ float  sProb[RB * CNUM];    // 35328 B
    __shared__ float  sDup[RB * 10];       // {cx,cx,cy,cy,w,w,h,h,A,A} per row, 3840 B
    __shared__ float4 sXY[RB];             // row xyxy, 1536 B

    const int tid = threadIdx.x;
    const int r0  = blockIdx.x * RB;
    const int t0  = blockIdx.y * 1024 + tid * 4;

    // Stage probmod rows (contiguous float4 copies)
    {
        const float4* gp = reinterpret_cast<const float4*>(g_prob + (size_t)r0 * CNUM);
        float4* sp = reinterpret_cast<float4*>(sProb);
        #pragma unroll 1
        for (int i = tid; i < RB * (CNUM / 4); i += 256) sp[i] = gp[i];
    }
    // Row features (duplicated for packed math) + xyxy
    if (tid < RB) {
        float4 b = reinterpret_cast<const float4*>(pred_boxes)[r0 + tid];
        float* d = sDup + tid * 10;
        d[0] = d[1] = b.x;  d[2] = d[3] = b.y;
        d[4] = d[5] = b.z;  d[6] = d[7] = b.w;
        float a = b.z * b.w; d[8] = d[9] = a;
        float hw = 0.5f * b.z, hh = 0.5f * b.w;
        sXY[tid] = make_float4(b.x - hw, b.y - hh, b.x + hw, b.y + hh);
    }
    __syncthreads();

    // Build the two loop-invariant target packs
    TPack T0, T1;
    {
        float4 A0 = g_tf[(t0 + 0) * 3 + 0], A1 = g_tf[(t0 + 0) * 3 + 1], A2 = g_tf[(t0 + 0) * 3 + 2];
        float4 B0 = g_tf[(t0 + 1) * 3 + 0], B1 = g_tf[(t0 + 1) * 3 + 1], B2 = g_tf[(t0 + 1) * 3 + 2];
        T0.cx = mk2(A0.x, B0.x); T0.cy = mk2(A0.y, B0.y);
        T0.w  = mk2(A0.z, B0.z); T0.h  = mk2(A0.w, B0.w);
        T0.area = mk2(A2.x, B2.x);
        T0.ax0 = A1.x; T0.ay0 = A1.y; T0.ax1 = A1.z; T0.ay1 = A1.w;
        T0.bx0 = B1.x; T0.by0 = B1.y; T0.bx1 = B1.z; T0.by1 = B1.w;
        T0.la = __float_as_int(A2.y); T0.lb = __float_as_int(B2.y);
    }
    {
        float4 A0 = g_tf[(t0 + 2) * 3 + 0], A1 = g_tf[(t0 + 2) * 3 + 1], A2 = g_tf[(t0 + 2) * 3 + 2];
        float4 B0 = g_tf[(t0 + 3) * 3 + 0], B1 = g_tf[(t0 + 3) * 3 + 1], B2 = g_tf[(t0 + 3) * 3 + 2];
        T1.cx = mk2(A0.x, B0.x); T1.cy = mk2(A0.y, B0.y);
        T1.w  = mk2(A0.z, B0.z); T1.h  = mk2(A0.w, B0.w);
        T1.area = mk2(A2.x, B2.x);
        T1.ax0 = A1.x; T1.ay0 = A1.y; T1.ax1 = A1.z; T1.ay1 = A1.w;
        T1.bx0 = B1.x; T1.by0 = B1.y; T1.bx1 = B1.z; T1.by1 = B1.w;
        T1.la = __float_as_int(A2.y); T1.lb = __float_as_int(B2.y);
    }

    const P2 c5  = mk2(5.f, 5.f);
    const P2 cm2 = mk2(-2.f, -2.f);

    float4* op = reinterpret_cast<float4*>(out + (size_t)r0 * TNUM + t0);
    const int strideF4 = TNUM / 4;

    #pragma unroll 1
    for (int i = 0; i < RB; i++) {
        const P2* rp = reinterpret_cast<const P2*>(sDup + i * 10);
        P2 rcx = rp[0], rcy = rp[1], rw = rp[2], rh = rp[3], rA = rp[4];
        float4 rx = sXY[i];
        const float* pr = sProb + i * CNUM;

        P2 resA = pack_cost(rcx, rcy, rw, rh, rA, rx, T0, pr, c5, cm2);
        P2 resB = pack_cost(rcx, rcy, rw, rh, rA, rx, T1, pr, c5, cm2);

        op[(size_t)i * strideF4] = make_float4(resA.f.x, resA.f.y, resB.f.x, resB.f.y);
    }
}

// ---------------------------------------------------------------------------
extern "C" void kernel_launch(void* const* d_in, const int* in_sizes, int n_in,
                              void* d_out, int out_size) {
    const float* logits  = (const float*)d_in[0];   // [32,900,92] f32
    const float* pboxes  = (const float*)d_in[1];   // [32,900,4]  f32
    const int*   tlabels = (const int*)  d_in[2];   // [2048] i32
    const float* tboxes  = (const float*)d_in[3];   // [2048,4] f32
    float* out = (float*)d_out;                      // [32,900,2048] f32

    softmax_kernel<<<BQ / 8, 256>>>(logits);
    tfeat_kernel<<<TNUM / 256, 256>>>(tboxes, tlabels);

    dim3 grid(BQ / RB, TNUM / 1024);  // (300, 2)
    cost_kernel<<<grid, 256>>>(pboxes, out);
}